// round 12
// baseline (speedup 1.0000x reference)
#include <cuda_runtime.h>
#include <cuda_bf16.h>
#include <cstdint>

#define NNODES 100000
#define NEDGES 1200000
#define DIM 64

// Scratch: agg = scatter_sum(relu(x[src]+edge_attr)); zeroed via memset node.
__device__ float g_agg[(size_t)NNODES * DIM];

// ---------------------------------------------------------------------------
// 256-bit L2-policy-hinted loads (ptxas requires .v8.b32/.v4.b64 with hints)
// ---------------------------------------------------------------------------
struct F8 { float v[8]; };

__device__ __forceinline__ F8 ldg_keep_v8(const float* p) {     // pin in L2
    unsigned r0, r1, r2, r3, r4, r5, r6, r7;
    asm("ld.global.nc.L2::evict_last.v8.b32 {%0,%1,%2,%3,%4,%5,%6,%7}, [%8];"
        : "=r"(r0), "=r"(r1), "=r"(r2), "=r"(r3),
          "=r"(r4), "=r"(r5), "=r"(r6), "=r"(r7) : "l"(p));
    F8 f;
    f.v[0] = __uint_as_float(r0); f.v[1] = __uint_as_float(r1);
    f.v[2] = __uint_as_float(r2); f.v[3] = __uint_as_float(r3);
    f.v[4] = __uint_as_float(r4); f.v[5] = __uint_as_float(r5);
    f.v[6] = __uint_as_float(r6); f.v[7] = __uint_as_float(r7);
    return f;
}
__device__ __forceinline__ F8 ldg_stream_v8(const float* p) {   // stream, discard
    unsigned r0, r1, r2, r3, r4, r5, r6, r7;
    asm("ld.global.nc.L2::evict_first.v8.b32 {%0,%1,%2,%3,%4,%5,%6,%7}, [%8];"
        : "=r"(r0), "=r"(r1), "=r"(r2), "=r"(r3),
          "=r"(r4), "=r"(r5), "=r"(r6), "=r"(r7) : "l"(p));
    F8 f;
    f.v[0] = __uint_as_float(r0); f.v[1] = __uint_as_float(r1);
    f.v[2] = __uint_as_float(r2); f.v[3] = __uint_as_float(r3);
    f.v[4] = __uint_as_float(r4); f.v[5] = __uint_as_float(r5);
    f.v[6] = __uint_as_float(r6); f.v[7] = __uint_as_float(r7);
    return f;
}
__device__ __forceinline__ void red_add_v4(float* addr, float a, float b, float c, float d) {
    asm volatile("red.global.add.v4.f32 [%0], {%1, %2, %3, %4};"
                 :: "l"(addr), "f"(a), "f"(b), "f"(c), "f"(d)
                 : "memory");
}

// ---------------------------------------------------------------------------
// Edge kernel: 8 threads/edge, 8 contiguous floats (32B) per thread.
//   m = relu(x[src] + edge_attr[e]);  agg[dst] += m
// ---------------------------------------------------------------------------
__global__ __launch_bounds__(256)
void edge_kernel(const float* __restrict__ x,
                 const int* __restrict__ edge_index,
                 const float* __restrict__ edge_attr,
                 float* __restrict__ agg) {
    unsigned g = blockIdx.x * blockDim.x + threadIdx.x;   // < 9.6M, fits u32
    unsigned e = g >> 3;                                  // edge id
    unsigned c = (g & 7u) << 3;                           // float offset in row
    if (e >= NEDGES) return;

    unsigned src = (unsigned)edge_index[e];               // broadcast within group
    unsigned dst = (unsigned)edge_index[NEDGES + e];

    // x is 25.6MB: pin in L2. edge_attr is 307MB: stream through.
    F8 xv = ldg_keep_v8(x + src * DIM + c);
    F8 ev = ldg_stream_v8(edge_attr + (size_t)e * DIM + c);

    float m[8];
    #pragma unroll
    for (int i = 0; i < 8; i++) m[i] = fmaxf(xv.v[i] + ev.v[i], 0.0f);

    float* a = agg + dst * DIM + c;
    red_add_v4(a,     m[0], m[1], m[2], m[3]);
    red_add_v4(a + 4, m[4], m[5], m[6], m[7]);
}

// ---------------------------------------------------------------------------
// Fused MLP: out = relu((x + agg) @ W1 + b1) @ W2 + b2
//   W1, W2 + biases staged in shared; one row per thread; W as broadcast LDS.128.
// ---------------------------------------------------------------------------
__global__ __launch_bounds__(256, 1)
void mlp_kernel(const float* __restrict__ x,
                const float* __restrict__ agg,
                const float* __restrict__ W1, const float* __restrict__ b1,
                const float* __restrict__ W2, const float* __restrict__ b2,
                float* __restrict__ out, int n) {
    __shared__ float4 sW1[DIM * (DIM / 4)];   // sW1[k*16 + c4] = W1[k][4c4..4c4+3]
    __shared__ float4 sW2[DIM * (DIM / 4)];
    __shared__ float  sb1[DIM];
    __shared__ float  sb2[DIM];

    const int tid = threadIdx.x;
    const float4* W1v = reinterpret_cast<const float4*>(W1);
    const float4* W2v = reinterpret_cast<const float4*>(W2);
    for (int i = tid; i < DIM * (DIM / 4); i += blockDim.x) {
        sW1[i] = W1v[i];
        sW2[i] = W2v[i];
    }
    if (tid < DIM) { sb1[tid] = b1[tid]; sb2[tid] = b2[tid]; }
    __syncthreads();

    const int row = blockIdx.x * blockDim.x + tid;
    if (row >= n) return;

    // h row = x row + agg row (16 x float4 each)
    float hr[DIM];
    const float4* xrow4 = reinterpret_cast<const float4*>(x   + (size_t)row * DIM);
    const float4* arow4 = reinterpret_cast<const float4*>(agg + (size_t)row * DIM);
    #pragma unroll
    for (int k4 = 0; k4 < DIM / 4; k4++) {
        float4 xv = xrow4[k4];
        float4 av = arow4[k4];
        hr[4 * k4 + 0] = xv.x + av.x;
        hr[4 * k4 + 1] = xv.y + av.y;
        hr[4 * k4 + 2] = xv.z + av.z;
        hr[4 * k4 + 3] = xv.w + av.w;
    }

    // Layer 1: t = relu(hr @ W1 + b1)
    float t[DIM];
    #pragma unroll
    for (int c4 = 0; c4 < DIM / 4; c4++) {
        float a0 = sb1[4 * c4 + 0], a1 = sb1[4 * c4 + 1];
        float a2 = sb1[4 * c4 + 2], a3 = sb1[4 * c4 + 3];
        #pragma unroll
        for (int k = 0; k < DIM; k++) {
            float4 w = sW1[k * (DIM / 4) + c4];   // warp-broadcast
            a0 = fmaf(hr[k], w.x, a0);
            a1 = fmaf(hr[k], w.y, a1);
            a2 = fmaf(hr[k], w.z, a2);
            a3 = fmaf(hr[k], w.w, a3);
        }
        t[4 * c4 + 0] = fmaxf(a0, 0.0f);
        t[4 * c4 + 1] = fmaxf(a1, 0.0f);
        t[4 * c4 + 2] = fmaxf(a2, 0.0f);
        t[4 * c4 + 3] = fmaxf(a3, 0.0f);
    }

    // Layer 2: out = t @ W2 + b2
    float4* orow4 = reinterpret_cast<float4*>(out + (size_t)row * DIM);
    #pragma unroll
    for (int c4 = 0; c4 < DIM / 4; c4++) {
        float a0 = sb2[4 * c4 + 0], a1 = sb2[4 * c4 + 1];
        float a2 = sb2[4 * c4 + 2], a3 = sb2[4 * c4 + 3];
        #pragma unroll
        for (int k = 0; k < DIM; k++) {
            float4 w = sW2[k * (DIM / 4) + c4];
            a0 = fmaf(t[k], w.x, a0);
            a1 = fmaf(t[k], w.y, a1);
            a2 = fmaf(t[k], w.z, a2);
            a3 = fmaf(t[k], w.w, a3);
        }
        float4 o; o.x = a0; o.y = a1; o.z = a2; o.w = a3;
        orow4[c4] = o;
    }
}

// ---------------------------------------------------------------------------
// Launch
// ---------------------------------------------------------------------------
extern "C" void kernel_launch(void* const* d_in, const int* in_sizes, int n_in,
                              void* d_out, int out_size) {
    const float* x          = (const float*)d_in[0];
    const int*   edge_index = (const int*)d_in[1];   // int32: JAX x64 disabled
    const float* edge_attr  = (const float*)d_in[2];
    const float* W1         = (const float*)d_in[3];
    const float* b1         = (const float*)d_in[4];
    const float* W2         = (const float*)d_in[5];
    const float* b2         = (const float*)d_in[6];
    float*       out        = (float*)d_out;

    float* agg;
    cudaGetSymbolAddress((void**)&agg, g_agg);

    // 1) agg <- 0 (memset node: write-only, cheaper than a copy kernel)
    cudaMemsetAsync(agg, 0, (size_t)NNODES * DIM * sizeof(float));

    // 2) scatter relu(x[src]+edge_attr) into agg[dst]
    {
        long long total = (long long)NEDGES * 8;
        int threads = 256;
        int blocks = (int)((total + threads - 1) / threads);
        edge_kernel<<<blocks, threads>>>(x, edge_index, edge_attr, agg);
    }

    // 3) fused MLP on x + agg
    {
        int threads = 256;
        int blocks = (NNODES + threads - 1) / threads;
        mlp_kernel<<<blocks, threads>>>(x, agg, W1, b1, W2, b2, out, NNODES);
    }
}

// round 17
// speedup vs baseline: 1.0039x; 1.0039x over previous
#include <cuda_runtime.h>
#include <cuda_bf16.h>
#include <cstdint>

#define NNODES 100000
#define NEDGES 1200000
#define DIM 64

// Scratch: agg = scatter_sum(relu(x[src]+edge_attr)); zeroed via memset node.
__device__ float g_agg[(size_t)NNODES * DIM];

// ---------------------------------------------------------------------------
// 256-bit L2-policy-hinted loads (ptxas requires .v8.b32/.v4.b64 with hints)
// ---------------------------------------------------------------------------
struct F8 { float v[8]; };

__device__ __forceinline__ F8 ldg_keep_v8(const float* p) {     // pin in L2
    unsigned r0, r1, r2, r3, r4, r5, r6, r7;
    asm("ld.global.nc.L2::evict_last.v8.b32 {%0,%1,%2,%3,%4,%5,%6,%7}, [%8];"
        : "=r"(r0), "=r"(r1), "=r"(r2), "=r"(r3),
          "=r"(r4), "=r"(r5), "=r"(r6), "=r"(r7) : "l"(p));
    F8 f;
    f.v[0] = __uint_as_float(r0); f.v[1] = __uint_as_float(r1);
    f.v[2] = __uint_as_float(r2); f.v[3] = __uint_as_float(r3);
    f.v[4] = __uint_as_float(r4); f.v[5] = __uint_as_float(r5);
    f.v[6] = __uint_as_float(r6); f.v[7] = __uint_as_float(r7);
    return f;
}
__device__ __forceinline__ F8 ldg_stream_v8(const float* p) {   // stream, discard
    unsigned r0, r1, r2, r3, r4, r5, r6, r7;
    asm("ld.global.nc.L2::evict_first.v8.b32 {%0,%1,%2,%3,%4,%5,%6,%7}, [%8];"
        : "=r"(r0), "=r"(r1), "=r"(r2), "=r"(r3),
          "=r"(r4), "=r"(r5), "=r"(r6), "=r"(r7) : "l"(p));
    F8 f;
    f.v[0] = __uint_as_float(r0); f.v[1] = __uint_as_float(r1);
    f.v[2] = __uint_as_float(r2); f.v[3] = __uint_as_float(r3);
    f.v[4] = __uint_as_float(r4); f.v[5] = __uint_as_float(r5);
    f.v[6] = __uint_as_float(r6); f.v[7] = __uint_as_float(r7);
    return f;
}
__device__ __forceinline__ void red_add_v4(float* addr, float a, float b, float c, float d) {
    asm volatile("red.global.add.v4.f32 [%0], {%1, %2, %3, %4};"
                 :: "l"(addr), "f"(a), "f"(b), "f"(c), "f"(d)
                 : "memory");
}

// ---------------------------------------------------------------------------
// Edge kernel: 8 threads/edge, 8 contiguous floats (32B) per thread.
//   m = relu(x[src] + edge_attr[e]);  agg[dst] += m
// ---------------------------------------------------------------------------
__global__ __launch_bounds__(256)
void edge_kernel(const float* __restrict__ x,
                 const int* __restrict__ edge_index,
                 const float* __restrict__ edge_attr,
                 float* __restrict__ agg) {
    unsigned g = blockIdx.x * blockDim.x + threadIdx.x;   // < 9.6M, fits u32
    unsigned e = g >> 3;                                  // edge id
    unsigned c = (g & 7u) << 3;                           // float offset in row
    if (e >= NEDGES) return;

    unsigned src = (unsigned)edge_index[e];               // broadcast within group
    unsigned dst = (unsigned)edge_index[NEDGES + e];

    // x is 25.6MB: pin in L2. edge_attr is 307MB: stream through.
    F8 xv = ldg_keep_v8(x + src * DIM + c);
    F8 ev = ldg_stream_v8(edge_attr + (size_t)e * DIM + c);

    float m[8];
    #pragma unroll
    for (int i = 0; i < 8; i++) m[i] = fmaxf(xv.v[i] + ev.v[i], 0.0f);

    float* a = agg + dst * DIM + c;
    red_add_v4(a,     m[0], m[1], m[2], m[3]);
    red_add_v4(a + 4, m[4], m[5], m[6], m[7]);
}

// ---------------------------------------------------------------------------
// Fused MLP: out = relu((x + agg) @ W1 + b1) @ W2 + b2
//   W1, W2 + biases staged in shared; one row per thread; W as broadcast LDS.128.
// ---------------------------------------------------------------------------
__global__ __launch_bounds__(256, 1)
void mlp_kernel(const float* __restrict__ x,
                const float* __restrict__ agg,
                const float* __restrict__ W1, const float* __restrict__ b1,
                const float* __restrict__ W2, const float* __restrict__ b2,
                float* __restrict__ out, int n) {
    __shared__ float4 sW1[DIM * (DIM / 4)];   // sW1[k*16 + c4] = W1[k][4c4..4c4+3]
    __shared__ float4 sW2[DIM * (DIM / 4)];
    __shared__ float  sb1[DIM];
    __shared__ float  sb2[DIM];

    const int tid = threadIdx.x;
    const float4* W1v = reinterpret_cast<const float4*>(W1);
    const float4* W2v = reinterpret_cast<const float4*>(W2);
    for (int i = tid; i < DIM * (DIM / 4); i += blockDim.x) {
        sW1[i] = W1v[i];
        sW2[i] = W2v[i];
    }
    if (tid < DIM) { sb1[tid] = b1[tid]; sb2[tid] = b2[tid]; }
    __syncthreads();

    const int row = blockIdx.x * blockDim.x + tid;
    if (row >= n) return;

    // h row = x row + agg row (16 x float4 each)
    float hr[DIM];
    const float4* xrow4 = reinterpret_cast<const float4*>(x   + (size_t)row * DIM);
    const float4* arow4 = reinterpret_cast<const float4*>(agg + (size_t)row * DIM);
    #pragma unroll
    for (int k4 = 0; k4 < DIM / 4; k4++) {
        float4 xv = xrow4[k4];
        float4 av = arow4[k4];
        hr[4 * k4 + 0] = xv.x + av.x;
        hr[4 * k4 + 1] = xv.y + av.y;
        hr[4 * k4 + 2] = xv.z + av.z;
        hr[4 * k4 + 3] = xv.w + av.w;
    }

    // Layer 1: t = relu(hr @ W1 + b1)
    float t[DIM];
    #pragma unroll
    for (int c4 = 0; c4 < DIM / 4; c4++) {
        float a0 = sb1[4 * c4 + 0], a1 = sb1[4 * c4 + 1];
        float a2 = sb1[4 * c4 + 2], a3 = sb1[4 * c4 + 3];
        #pragma unroll
        for (int k = 0; k < DIM; k++) {
            float4 w = sW1[k * (DIM / 4) + c4];   // warp-broadcast
            a0 = fmaf(hr[k], w.x, a0);
            a1 = fmaf(hr[k], w.y, a1);
            a2 = fmaf(hr[k], w.z, a2);
            a3 = fmaf(hr[k], w.w, a3);
        }
        t[4 * c4 + 0] = fmaxf(a0, 0.0f);
        t[4 * c4 + 1] = fmaxf(a1, 0.0f);
        t[4 * c4 + 2] = fmaxf(a2, 0.0f);
        t[4 * c4 + 3] = fmaxf(a3, 0.0f);
    }

    // Layer 2: out = t @ W2 + b2
    float4* orow4 = reinterpret_cast<float4*>(out + (size_t)row * DIM);
    #pragma unroll
    for (int c4 = 0; c4 < DIM / 4; c4++) {
        float a0 = sb2[4 * c4 + 0], a1 = sb2[4 * c4 + 1];
        float a2 = sb2[4 * c4 + 2], a3 = sb2[4 * c4 + 3];
        #pragma unroll
        for (int k = 0; k < DIM; k++) {
            float4 w = sW2[k * (DIM / 4) + c4];
            a0 = fmaf(t[k], w.x, a0);
            a1 = fmaf(t[k], w.y, a1);
            a2 = fmaf(t[k], w.z, a2);
            a3 = fmaf(t[k], w.w, a3);
        }
        float4 o; o.x = a0; o.y = a1; o.z = a2; o.w = a3;
        orow4[c4] = o;
    }
}

// ---------------------------------------------------------------------------
// Launch
// ---------------------------------------------------------------------------
extern "C" void kernel_launch(void* const* d_in, const int* in_sizes, int n_in,
                              void* d_out, int out_size) {
    const float* x          = (const float*)d_in[0];
    const int*   edge_index = (const int*)d_in[1];   // int32: JAX x64 disabled
    const float* edge_attr  = (const float*)d_in[2];
    const float* W1         = (const float*)d_in[3];
    const float* b1         = (const float*)d_in[4];
    const float* W2         = (const float*)d_in[5];
    const float* b2         = (const float*)d_in[6];
    float*       out        = (float*)d_out;

    float* agg;
    cudaGetSymbolAddress((void**)&agg, g_agg);

    // 1) agg <- 0 (memset node: write-only, cheaper than a copy kernel)
    cudaMemsetAsync(agg, 0, (size_t)NNODES * DIM * sizeof(float));

    // 2) scatter relu(x[src]+edge_attr) into agg[dst]
    {
        long long total = (long long)NEDGES * 8;
        int threads = 256;
        int blocks = (int)((total + threads - 1) / threads);
        edge_kernel<<<blocks, threads>>>(x, edge_index, edge_attr, agg);
    }

    // 3) fused MLP on x + agg
    {
        int threads = 256;
        int blocks = (NNODES + threads - 1) / threads;
        mlp_kernel<<<blocks, threads>>>(x, agg, W1, b1, W2, b2, out, NNODES);
    }
}